// round 16
// baseline (speedup 1.0000x reference)
#include <cuda_runtime.h>
#include <cuda_fp16.h>
#include <cstdint>

// ---------------------------------------------------------------------------
// SparseColumnAttention via mma.sync pure-fp16 GEMMs (sm_100 baseline).
//   x:(2,128,45,512) f32 -> R=11520 rows, C=512, N=8 heads, D=64, K=17.
// R16: R15 design (attention fully on tensor cores: S=Q@K^T and O=P@V with
//      dense-ified fp16 weight matrix P; O C-frags stored directly as g_aatt
//      A-frags) with the alignment bug fixed: all shared arrays accessed via
//      wider types are __align__(16).
// Error model: + fp16 rounding of weights (2.4e-4) => ~5.3e-4 total (gate 1e-3).
// ---------------------------------------------------------------------------

#define ROWS 11520

__device__ __half   g_qkv[ROWS * 1536];
__device__ uint32_t g_ax  [ROWS * 256];   // [90 mtile][16 kc][2048 u32]
__device__ uint32_t g_aatt[ROWS * 256];   // same layout (written by attn)
__device__ uint32_t g_bw1 [1536 * 256];   // [12 ntile][16 kc][2048 u32]
__device__ uint32_t g_bw2 [512 * 256];    // [4 ntile][...]
__device__ float    g_bias[1536];

// ------------------------------ helpers -----------------------------------
__device__ __forceinline__ uint32_t s2u32(const void* p) {
    uint32_t a;
    asm("{ .reg .u64 t; cvta.to.shared.u64 t, %1; cvt.u32.u64 %0, t; }"
        : "=r"(a) : "l"(p));
    return a;
}
__device__ __forceinline__ void cp16(uint32_t s, const void* g) {
    asm volatile("cp.async.cg.shared.global [%0], [%1], 16;" :: "r"(s), "l"(g));
}
#define CP_COMMIT() asm volatile("cp.async.commit_group;" ::: "memory")
#define CP_WAIT(n)  asm volatile("cp.async.wait_group %0;" :: "n"(n) : "memory")

__device__ __forceinline__ void lds128(uint32_t* r, uint32_t a) {
    asm volatile("ld.shared.v4.b32 {%0,%1,%2,%3}, [%4];"
                 : "=r"(r[0]), "=r"(r[1]), "=r"(r[2]), "=r"(r[3]) : "r"(a));
}
__device__ __forceinline__ void lds64(uint32_t* r, uint32_t a) {
    asm volatile("ld.shared.v2.b32 {%0,%1}, [%2];"
                 : "=r"(r[0]), "=r"(r[1]) : "r"(a));
}
__device__ __forceinline__ void mma_fp16(float* c, const uint32_t* a, const uint32_t* b) {
    asm volatile(
        "mma.sync.aligned.m16n8k16.row.col.f32.f16.f16.f32 "
        "{%0,%1,%2,%3}, {%4,%5,%6,%7}, {%8,%9}, {%0,%1,%2,%3};"
        : "+f"(c[0]), "+f"(c[1]), "+f"(c[2]), "+f"(c[3])
        : "r"(a[0]), "r"(a[1]), "r"(a[2]), "r"(a[3]), "r"(b[0]), "r"(b[1]));
}

// ------------------------------ pack (all) ---------------------------------
// blocks [0,1440): pack x -> g_ax (smem-staged); [1440,1632): W_qkv (+bias);
// [1632,1696): Wp -> g_bw2
__global__ __launch_bounds__(256)
void pack_all(const float* __restrict__ x,
              const float* __restrict__ Wq, const float* __restrict__ Wk,
              const float* __restrict__ Wv, const float* __restrict__ Wp,
              const float* __restrict__ bq, const float* __restrict__ bk,
              const float* __restrict__ bv)
{
    __shared__ __align__(16) float xs[128 * 32];
    const int b = blockIdx.x, t = threadIdx.x;
    if (b < 1440) {
        const int mtile = b >> 4, kc = b & 15;
        const float* src = x + (size_t)mtile * 128 * 512 + kc * 32;
#pragma unroll
        for (int i = 0; i < 4; i++) {
            int idx = t + i * 256;
            int row = idx >> 3;
            int c4 = (idx & 7) * 4;
            *(float4*)&xs[row * 32 + c4] = *(const float4*)(src + (size_t)row * 512 + c4);
        }
        __syncthreads();

        uint32_t* chunk = g_ax + ((size_t)mtile * 16 + kc) * 2048;
#pragma unroll
        for (int s = 0; s < 8; s++) {
            int p = t + s * 256;
            int blk = p >> 7, q = p & 127;
            int lane = q >> 2, reg = q & 3;
            int mb = blk >> 1, kb = blk & 1;
            int row = mb * 16 + (lane >> 2) + 8 * (reg & 1);
            int col = kb * 16 + (lane & 3) * 2 + 8 * (reg >> 1);
            float2 v = *(const float2*)&xs[row * 32 + col];
            __half2 h = __floats2half2_rn(v.x, v.y);
            chunk[p] = *(uint32_t*)&h;
        }
        return;
    }
    const int wb = b - 1440;
    const int is_p = wb >= 192;
    const int lb = is_p ? wb - 192 : wb;
    if (!is_p && wb < 6) {
        int i = wb * 256 + t;
        g_bias[i] = (i < 512) ? bq[i] : (i < 1024 ? bk[i - 512] : bv[i - 1024]);
    }
    uint32_t* dst = is_p ? g_bw2 : g_bw1;
    const int ntile = lb >> 4, kc = lb & 15;
    uint32_t* chunk = dst + ((size_t)ntile * 16 + kc) * 2048;
#pragma unroll
    for (int s = 0; s < 8; s++) {
        int p = t + s * 256;
        int blk = p >> 6, q = p & 63;
        int lane = q >> 1, reg = q & 1;
        int nb = blk >> 1, kb = blk & 1;
        int n = ntile * 128 + nb * 8 + (lane >> 2);
        int col = kc * 32 + kb * 16 + (lane & 3) * 2 + 8 * reg;
        const float* W = is_p ? Wp : ((n < 512) ? Wq : (n < 1024 ? Wk : Wv));
        float2 v = *(const float2*)(W + (size_t)(n & 511) * 512 + col);
        __half2 h = __floats2half2_rn(v.x, v.y);
        chunk[p] = *(uint32_t*)&h;
    }
}

// --------------------- GEMM QKV: 128x128 (R7 config) -----------------------
#define GSMEM (3 * 32768)

__global__ __launch_bounds__(256, 2)
void gemm_qkv(void)
{
    extern __shared__ __align__(16) char smem[];
    const uint32_t sb = s2u32(smem);
    const int t = threadIdx.x;
    const int wid = t >> 5, lane = t & 31;
    const int wm = wid & 1, wn = wid >> 1;

    const uint4* Ag = (const uint4*)g_ax + (size_t)blockIdx.x * 8192;
    const uint4* Bg = (const uint4*)g_bw1 + (size_t)blockIdx.y * 8192;

#define LOADS(c, stage) do {                                            \
        uint32_t s_ = sb + (stage) * 32768;                             \
        const uint4* ga_ = Ag + (c) * 1024 + t;                         \
        const uint4* gb_ = Bg + (c) * 1024 + t;                         \
        _Pragma("unroll")                                               \
        for (int i_ = 0; i_ < 4; i_++)                                  \
            cp16(s_ + (t + i_ * 256) * 16, ga_ + i_ * 256);             \
        _Pragma("unroll")                                               \
        for (int i_ = 0; i_ < 4; i_++)                                  \
            cp16(s_ + 16384 + (t + i_ * 256) * 16, gb_ + i_ * 256);     \
        CP_COMMIT();                                                    \
    } while (0)

    float acc[4][4][4];
#pragma unroll
    for (int i = 0; i < 4; i++)
#pragma unroll
        for (int j = 0; j < 4; j++)
#pragma unroll
            for (int r = 0; r < 4; r++) acc[i][j][r] = 0.f;

    LOADS(0, 0);
    LOADS(1, 1);

    uint32_t ah[2][4][4], bh[2][4][2];

    for (int c = 0; c < 8; c++) {
        if (c < 6) CP_WAIT(1);
        else       CP_WAIT(0);
        __syncthreads();

        if (c + 2 < 8) LOADS(c + 2, (c + 2) % 3);

        const uint32_t sa = sb + (c % 3) * 32768;
        const uint32_t sbm = sa + 16384;

#define AADDR(kb, i) (sa + (uint32_t)(((kb) >> 1) * 8192 + \
                       (((wm * 4 + (i)) * 2 + ((kb) & 1)) * 512 + lane * 16)))
#define BADDR(kb, j) (sbm + (uint32_t)(((kb) >> 1) * 8192 + \
                       (((wn * 4 + (j)) * 2 + ((kb) & 1)) * 256 + lane * 8)))

#pragma unroll
        for (int i = 0; i < 4; i++) lds128(ah[0][i], AADDR(0, i));
#pragma unroll
        for (int j = 0; j < 4; j++) lds64(bh[0][j], BADDR(0, j));

#pragma unroll
        for (int kb = 0; kb < 4; kb++) {
            const int cur = kb & 1, nxt = cur ^ 1;
            if (kb < 3) {
#pragma unroll
                for (int i = 0; i < 4; i++) lds128(ah[nxt][i], AADDR(kb + 1, i));
#pragma unroll
                for (int j = 0; j < 4; j++) lds64(bh[nxt][j], BADDR(kb + 1, j));
            }
#pragma unroll
            for (int i = 0; i < 4; i++)
#pragma unroll
                for (int j = 0; j < 4; j++)
                    mma_fp16(acc[i][j], ah[cur][i], bh[cur][j]);
        }
#undef AADDR
#undef BADDR
    }

    // epilogue: fp16 output (bias added in fp32, rounded once)
    const int row0 = blockIdx.x * 128 + wm * 64 + (lane >> 2);
    const int colb = blockIdx.y * 128 + wn * 32 + (lane & 3) * 2;
#pragma unroll
    for (int i = 0; i < 4; i++)
#pragma unroll
        for (int j = 0; j < 4; j++) {
            const int r = row0 + i * 16;
            const int c = colb + j * 8;
            const float b0 = __ldg(g_bias + c), b1 = __ldg(g_bias + c + 1);
            __half2 h0 = __floats2half2_rn(acc[i][j][0] + b0, acc[i][j][1] + b1);
            __half2 h1 = __floats2half2_rn(acc[i][j][2] + b0, acc[i][j][3] + b1);
            *(__half2*)(g_qkv + (size_t)r * 1536 + c) = h0;
            *(__half2*)(g_qkv + (size_t)(r + 8) * 1536 + c) = h1;
        }
#undef LOADS
}

// --------------------- GEMM out-proj: 64x128 tiles (R9) --------------------
#define GOSMEM (3 * 24576)

__global__ __launch_bounds__(256, 2)
void gemm_o(const float* __restrict__ bias, float* __restrict__ C)
{
    extern __shared__ __align__(16) char smem[];
    const uint32_t sb = s2u32(smem);
    const int t = threadIdx.x;
    const int wid = t >> 5, lane = t & 31;
    const int wm = wid & 1, wn = wid >> 1;

    const int mtile = blockIdx.x >> 1, mh = blockIdx.x & 1;
    const uint4* Ag = (const uint4*)g_aatt + (size_t)mtile * 8192;
    const uint4* Bg = (const uint4*)g_bw2 + (size_t)blockIdx.y * 8192;

#define LOADO(c, stage) do {                                            \
        uint32_t s_ = sb + (stage) * 24576;                             \
        const uint4* ga0_ = Ag + (c) * 1024 + mh * 256 + t;             \
        const uint4* ga1_ = Ag + (c) * 1024 + 512 + mh * 256 + t;       \
        cp16(s_ + t * 16, ga0_);                                        \
        cp16(s_ + 4096 + t * 16, ga1_);                                 \
        const uint4* gb_ = Bg + (c) * 1024 + t;                         \
        _Pragma("unroll")                                               \
        for (int i_ = 0; i_ < 4; i_++)                                  \
            cp16(s_ + 8192 + (t + i_ * 256) * 16, gb_ + i_ * 256);      \
        CP_COMMIT();                                                    \
    } while (0)

    float acc[2][4][4];
#pragma unroll
    for (int i = 0; i < 2; i++)
#pragma unroll
        for (int j = 0; j < 4; j++)
#pragma unroll
            for (int r = 0; r < 4; r++) acc[i][j][r] = 0.f;

    LOADO(0, 0);
    LOADO(1, 1);

    uint32_t ah[2][2][4], bh[2][4][2];

    for (int c = 0; c < 8; c++) {
        if (c < 6) CP_WAIT(1);
        else       CP_WAIT(0);
        __syncthreads();

        if (c + 2 < 8) LOADO(c + 2, (c + 2) % 3);

        const uint32_t sa = sb + (c % 3) * 24576;
        const uint32_t sbm = sa + 8192;

#define AADDR(kb, i) (sa + (uint32_t)(((kb) >> 1) * 4096 + \
                       (((wm * 2 + (i)) * 2 + ((kb) & 1)) * 512 + lane * 16)))
#define BADDR(kb, j) (sbm + (uint32_t)(((kb) >> 1) * 8192 + \
                       (((wn * 4 + (j)) * 2 + ((kb) & 1)) * 256 + lane * 8)))

#pragma unroll
        for (int i = 0; i < 2; i++) lds128(ah[0][i], AADDR(0, i));
#pragma unroll
        for (int j = 0; j < 4; j++) lds64(bh[0][j], BADDR(0, j));

#pragma unroll
        for (int kb = 0; kb < 4; kb++) {
            const int cur = kb & 1, nxt = cur ^ 1;
            if (kb < 3) {
#pragma unroll
                for (int i = 0; i < 2; i++) lds128(ah[nxt][i], AADDR(kb + 1, i));
#pragma unroll
                for (int j = 0; j < 4; j++) lds64(bh[nxt][j], BADDR(kb + 1, j));
            }
#pragma unroll
            for (int i = 0; i < 2; i++)
#pragma unroll
                for (int j = 0; j < 4; j++)
                    mma_fp16(acc[i][j], ah[cur][i], bh[cur][j]);
        }
#undef AADDR
#undef BADDR
    }

    const int row0 = blockIdx.x * 64 + wm * 32 + (lane >> 2);
    const int colb = blockIdx.y * 128 + wn * 32 + (lane & 3) * 2;
#pragma unroll
    for (int i = 0; i < 2; i++)
#pragma unroll
        for (int j = 0; j < 4; j++) {
            const int r = row0 + i * 16;
            const int c = colb + j * 8;
            const float b0 = __ldg(bias + c), b1 = __ldg(bias + c + 1);
            *(float2*)(C + (size_t)r * 512 + c) =
                make_float2(acc[i][j][0] + b0, acc[i][j][1] + b1);
            *(float2*)(C + (size_t)(r + 8) * 512 + c) =
                make_float2(acc[i][j][2] + b0, acc[i][j][3] + b1);
        }
#undef LOADO
}

// ----------------------------- attention -----------------------------------
// block=(bm, head).
//  P1: stage sp, V rows, Q/K fragment chunks; zero P.
//  P2: build V B-fragments; Gram S = Q@K^T via 18 mmas.
//  P3: warp-per-query softmax over 17 S entries; scatter fp16 weights into P.
//  P4: O = P@V via 24 mma tiles; C-fragments stored directly as g_aatt
//      A-fragments (masked rows >= 45).
__global__ __launch_bounds__(256)
void attn_kernel(const int* __restrict__ pair_idxs)
{
    __shared__ __align__(16) int      sp[45 * 17];
    __shared__ __align__(16) __half   vsh[45 * 64];
    __shared__ __align__(16) uint32_t qf[1536];   // Q A-frags: [mb(3)][kb(4)][128]
    __shared__ __align__(16) uint32_t kf[1536];   // K B-frags: [nb(6)][kb(4)][64]
    __shared__ __align__(16) uint32_t vf[1536];   // V B-frags: [kb(3)][nb(8)][64]
    __shared__ __align__(16) float    S[48 * 52];
    __shared__ __align__(16) __half   P[48 * 48];

    const int bm = blockIdx.x;   // 0..255
    const int n = blockIdx.y;    // 0..7
    const int base = bm * 45;
    const int tid = threadIdx.x;

    for (int i = tid; i < 45 * 17; i += 256) sp[i] = pair_idxs[i];
    for (int i = tid; i < 45 * 8; i += 256) {
        const int r = i >> 3, seg = i & 7;
        ((uint4*)vsh)[r * 8 + seg] =
            ((const uint4*)(g_qkv + (size_t)(base + r) * 1536 + 1024 + n * 64))[seg];
    }
    for (int i = tid; i < 1152; i += 256) ((uint32_t*)P)[i] = 0;
    // Q fragments
    for (int p = tid; p < 1536; p += 256) {
        const int mbkb = p >> 7, q = p & 127;
        const int mb = mbkb >> 2, kb = mbkb & 3;
        const int lane = q >> 2, reg = q & 3;
        const int row = mb * 16 + (lane >> 2) + 8 * (reg & 1);
        const int col = kb * 16 + (lane & 3) * 2 + 8 * (reg >> 1);
        uint32_t v = 0;
        if (row < 45)
            v = *(const uint32_t*)(g_qkv + (size_t)(base + row) * 1536 + n * 64 + col);
        qf[p] = v;
    }
    // K fragments
    for (int p = tid; p < 1536; p += 256) {
        const int nbkb = p >> 6, q = p & 63;
        const int nb = nbkb >> 2, kb = nbkb & 3;
        const int lane = q >> 1, reg = q & 1;
        const int nr = nb * 8 + (lane >> 2);
        const int col = kb * 16 + (lane & 3) * 2 + 8 * reg;
        uint32_t v = 0;
        if (nr < 45)
            v = *(const uint32_t*)(g_qkv + (size_t)(base + nr) * 1536 + 512 + n * 64 + col);
        kf[p] = v;
    }
    __syncthreads();

    const int warp = tid >> 5, lane = tid & 31;
    const uint32_t qfb = s2u32(qf), kfb = s2u32(kf);
    const uint32_t vfb = s2u32(vf);

    // V B-fragments (from vsh): vf[kb][nb][lane*2+reg] = half2(V[k0][nn], V[k0+1][nn])
    for (int p = tid; p < 1536; p += 256) {
        const int kb = p >> 9;
        const int nb = (p >> 6) & 7;
        const int q = p & 63;
        const int l = q >> 1, r = q & 1;
        const int nn = nb * 8 + (l >> 2);
        const int k0 = kb * 16 + (l & 3) * 2 + 8 * r;
        __half h0 = (k0 < 45) ? vsh[k0 * 64 + nn] : __float2half(0.f);
        __half h1 = (k0 + 1 < 45) ? vsh[(k0 + 1) * 64 + nn] : __float2half(0.f);
        __half2 hh = __halves2half2(h0, h1);
        vf[p] = *(uint32_t*)&hh;
    }

    // Gram: 18 tiles of 16x8, 4 k-steps each
    for (int t = warp; t < 18; t += 8) {
        const int mb = t / 6, nb = t % 6;
        float c[4] = {0.f, 0.f, 0.f, 0.f};
#pragma unroll
        for (int kb = 0; kb < 4; kb++) {
            uint32_t a[4], b[2];
            lds128(a, qfb + (uint32_t)(((mb * 4 + kb) * 128 + lane * 4) * 4));
            lds64(b, kfb + (uint32_t)(((nb * 4 + kb) * 64 + lane * 2) * 4));
            mma_fp16(c, a, b);
        }
        const int r0 = mb * 16 + (lane >> 2);
        const int c0 = nb * 8 + (lane & 3) * 2;
        *(float2*)&S[r0 * 52 + c0] = make_float2(c[0], c[1]);
        *(float2*)&S[(r0 + 8) * 52 + c0] = make_float2(c[2], c[3]);
    }
    __syncthreads();

    // softmax + scatter fp16 weights into P
    for (int tt = warp; tt < 45; tt += 8) {
        float sc[17];
        int tj[17];
#pragma unroll
        for (int j = 0; j < 17; j++) {
            tj[j] = sp[tt * 17 + j];
            sc[j] = S[tt * 52 + tj[j]] * 0.125f;
        }
        float mx = sc[0];
#pragma unroll
        for (int j = 1; j < 17; j++) mx = fmaxf(mx, sc[j]);
        float ssum = 0.f;
#pragma unroll
        for (int j = 0; j < 17; j++) { sc[j] = __expf(sc[j] - mx); ssum += sc[j]; }
        const float inv = 1.f / ssum;
        if (lane == 0) {
#pragma unroll
            for (int j = 0; j < 17; j++)
                P[tt * 48 + tj[j]] = __float2half(sc[j] * inv);
        }
    }
    __syncthreads();

    // O = P @ V : 24 tiles (3 mb x 8 nb) x 3 k-steps; store C frags to g_aatt
    for (int t = warp; t < 24; t += 8) {
        const int mb = t >> 3, nb = t & 7;
        float c[4] = {0.f, 0.f, 0.f, 0.f};
        const int prow = mb * 16 + (lane >> 2);
        const int pcl = (lane & 3) * 2;
#pragma unroll
        for (int kb = 0; kb < 3; kb++) {
            uint32_t a[4], b[2];
            const int col0 = kb * 16 + pcl;
            a[0] = *(const uint32_t*)&P[prow * 48 + col0];
            a[1] = *(const uint32_t*)&P[(prow + 8) * 48 + col0];
            a[2] = *(const uint32_t*)&P[prow * 48 + col0 + 8];
            a[3] = *(const uint32_t*)&P[(prow + 8) * 48 + col0 + 8];
            lds64(b, vfb + (uint32_t)(((kb * 8 + nb) * 64 + lane * 2) * 4));
            mma_fp16(c, a, b);
        }
        // C frag -> g_aatt A-frag (lane owns col pair jp), masked rows >= 45
        const int jp = nb * 4 + (lane & 3);
        const int kc = n * 2 + (jp >> 4);
        const int jpl = jp & 15;
#pragma unroll
        for (int h = 0; h < 2; h++) {
            const int r = prow + 8 * h;
            if (r < 45) {
                const int grow = base + r;
                const int mtile = grow >> 7;
                const int rr = grow & 127;
                const int lane_t = (rr & 7) * 4 + (jpl & 3);
                const int reg = ((rr >> 3) & 1) + 2 * ((jpl >> 2) & 1);
                const int kb2 = jpl >> 3;
                const int idx = ((rr >> 4) * 2 + kb2) * 128 + lane_t * 4 + reg;
                __half2 hh = __floats2half2_rn(c[2 * h], c[2 * h + 1]);
                g_aatt[((size_t)mtile * 16 + kc) * 2048 + idx] = *(uint32_t*)&hh;
            }
        }
    }
}

// ------------------------------- launch ------------------------------------
extern "C" void kernel_launch(void* const* d_in, const int* in_sizes, int n_in,
                              void* d_out, int out_size)
{
    const float* x  = (const float*)d_in[0];
    const float* Wq = (const float*)d_in[1];
    const float* bq = (const float*)d_in[2];
    const float* Wk = (const float*)d_in[3];
    const float* bk = (const float*)d_in[4];
    const float* Wv = (const float*)d_in[5];
    const float* bv = (const float*)d_in[6];
    const float* Wp = (const float*)d_in[7];
    const float* bp = (const float*)d_in[8];
    const int* pair = (const int*)d_in[9];
    float* out = (float*)d_out;
    (void)in_sizes; (void)n_in; (void)out_size;

    cudaFuncSetAttribute(gemm_qkv, cudaFuncAttributeMaxDynamicSharedMemorySize, GSMEM);
    cudaFuncSetAttribute(gemm_o, cudaFuncAttributeMaxDynamicSharedMemorySize, GOSMEM);

    pack_all<<<1696, 256>>>(x, Wq, Wk, Wv, Wp, bq, bk, bv);
    gemm_qkv<<<dim3(90, 12), 256, GSMEM>>>();
    attn_kernel<<<dim3(256, 8), 256>>>(pair);
    gemm_o<<<dim3(180, 4), 256, GOSMEM>>>(bp, out);
}

// round 17
// speedup vs baseline: 1.0700x; 1.0700x over previous
#include <cuda_runtime.h>
#include <cuda_fp16.h>
#include <cstdint>

// ---------------------------------------------------------------------------
// SparseColumnAttention via mma.sync pure-fp16 GEMMs (sm_100 baseline).
//   x:(2,128,45,512) f32 -> R=11520 rows, C=512, N=8 heads, D=64, K=17.
// R17: R14 design restored (tensor-core Gram S=Q@K^T + scalar softmax/V loop,
//      which measured faster than R16's O=P@V mma) with Q/K fragment staging
//      now via coalesced uint4 smem stage (was scattered 4B global loads).
// Error model (validated): ~4.75e-4 total (gate 1e-3).
// ---------------------------------------------------------------------------

#define ROWS 11520

__device__ __half   g_qkv[ROWS * 1536];
__device__ uint32_t g_ax  [ROWS * 256];   // [90 mtile][16 kc][2048 u32]
__device__ uint32_t g_aatt[ROWS * 256];   // same layout (written by attn)
__device__ uint32_t g_bw1 [1536 * 256];   // [12 ntile][16 kc][2048 u32]
__device__ uint32_t g_bw2 [512 * 256];    // [4 ntile][...]
__device__ float    g_bias[1536];

// ------------------------------ helpers -----------------------------------
__device__ __forceinline__ uint32_t s2u32(const void* p) {
    uint32_t a;
    asm("{ .reg .u64 t; cvta.to.shared.u64 t, %1; cvt.u32.u64 %0, t; }"
        : "=r"(a) : "l"(p));
    return a;
}
__device__ __forceinline__ void cp16(uint32_t s, const void* g) {
    asm volatile("cp.async.cg.shared.global [%0], [%1], 16;" :: "r"(s), "l"(g));
}
#define CP_COMMIT() asm volatile("cp.async.commit_group;" ::: "memory")
#define CP_WAIT(n)  asm volatile("cp.async.wait_group %0;" :: "n"(n) : "memory")

__device__ __forceinline__ void lds128(uint32_t* r, uint32_t a) {
    asm volatile("ld.shared.v4.b32 {%0,%1,%2,%3}, [%4];"
                 : "=r"(r[0]), "=r"(r[1]), "=r"(r[2]), "=r"(r[3]) : "r"(a));
}
__device__ __forceinline__ void lds64(uint32_t* r, uint32_t a) {
    asm volatile("ld.shared.v2.b32 {%0,%1}, [%2];"
                 : "=r"(r[0]), "=r"(r[1]) : "r"(a));
}
__device__ __forceinline__ void mma_fp16(float* c, const uint32_t* a, const uint32_t* b) {
    asm volatile(
        "mma.sync.aligned.m16n8k16.row.col.f32.f16.f16.f32 "
        "{%0,%1,%2,%3}, {%4,%5,%6,%7}, {%8,%9}, {%0,%1,%2,%3};"
        : "+f"(c[0]), "+f"(c[1]), "+f"(c[2]), "+f"(c[3])
        : "r"(a[0]), "r"(a[1]), "r"(a[2]), "r"(a[3]), "r"(b[0]), "r"(b[1]));
}

// ------------------------------ pack (all) ---------------------------------
// blocks [0,1440): pack x -> g_ax (smem-staged); [1440,1632): W_qkv (+bias);
// [1632,1696): Wp -> g_bw2
__global__ __launch_bounds__(256)
void pack_all(const float* __restrict__ x,
              const float* __restrict__ Wq, const float* __restrict__ Wk,
              const float* __restrict__ Wv, const float* __restrict__ Wp,
              const float* __restrict__ bq, const float* __restrict__ bk,
              const float* __restrict__ bv)
{
    __shared__ __align__(16) float xs[128 * 32];
    const int b = blockIdx.x, t = threadIdx.x;
    if (b < 1440) {
        const int mtile = b >> 4, kc = b & 15;
        const float* src = x + (size_t)mtile * 128 * 512 + kc * 32;
#pragma unroll
        for (int i = 0; i < 4; i++) {
            int idx = t + i * 256;
            int row = idx >> 3;
            int c4 = (idx & 7) * 4;
            *(float4*)&xs[row * 32 + c4] = *(const float4*)(src + (size_t)row * 512 + c4);
        }
        __syncthreads();

        uint32_t* chunk = g_ax + ((size_t)mtile * 16 + kc) * 2048;
#pragma unroll
        for (int s = 0; s < 8; s++) {
            int p = t + s * 256;
            int blk = p >> 7, q = p & 127;
            int lane = q >> 2, reg = q & 3;
            int mb = blk >> 1, kb = blk & 1;
            int row = mb * 16 + (lane >> 2) + 8 * (reg & 1);
            int col = kb * 16 + (lane & 3) * 2 + 8 * (reg >> 1);
            float2 v = *(const float2*)&xs[row * 32 + col];
            __half2 h = __floats2half2_rn(v.x, v.y);
            chunk[p] = *(uint32_t*)&h;
        }
        return;
    }
    const int wb = b - 1440;
    const int is_p = wb >= 192;
    const int lb = is_p ? wb - 192 : wb;
    if (!is_p && wb < 6) {
        int i = wb * 256 + t;
        g_bias[i] = (i < 512) ? bq[i] : (i < 1024 ? bk[i - 512] : bv[i - 1024]);
    }
    uint32_t* dst = is_p ? g_bw2 : g_bw1;
    const int ntile = lb >> 4, kc = lb & 15;
    uint32_t* chunk = dst + ((size_t)ntile * 16 + kc) * 2048;
#pragma unroll
    for (int s = 0; s < 8; s++) {
        int p = t + s * 256;
        int blk = p >> 6, q = p & 63;
        int lane = q >> 1, reg = q & 1;
        int nb = blk >> 1, kb = blk & 1;
        int n = ntile * 128 + nb * 8 + (lane >> 2);
        int col = kc * 32 + kb * 16 + (lane & 3) * 2 + 8 * reg;
        const float* W = is_p ? Wp : ((n < 512) ? Wq : (n < 1024 ? Wk : Wv));
        float2 v = *(const float2*)(W + (size_t)(n & 511) * 512 + col);
        __half2 h = __floats2half2_rn(v.x, v.y);
        chunk[p] = *(uint32_t*)&h;
    }
}

// --------------------- GEMM QKV: 128x128 (R7 config) -----------------------
#define GSMEM (3 * 32768)

__global__ __launch_bounds__(256, 2)
void gemm_qkv(void)
{
    extern __shared__ __align__(16) char smem[];
    const uint32_t sb = s2u32(smem);
    const int t = threadIdx.x;
    const int wid = t >> 5, lane = t & 31;
    const int wm = wid & 1, wn = wid >> 1;

    const uint4* Ag = (const uint4*)g_ax + (size_t)blockIdx.x * 8192;
    const uint4* Bg = (const uint4*)g_bw1 + (size_t)blockIdx.y * 8192;

#define LOADS(c, stage) do {                                            \
        uint32_t s_ = sb + (stage) * 32768;                             \
        const uint4* ga_ = Ag + (c) * 1024 + t;                         \
        const uint4* gb_ = Bg + (c) * 1024 + t;                         \
        _Pragma("unroll")                                               \
        for (int i_ = 0; i_ < 4; i_++)                                  \
            cp16(s_ + (t + i_ * 256) * 16, ga_ + i_ * 256);             \
        _Pragma("unroll")                                               \
        for (int i_ = 0; i_ < 4; i_++)                                  \
            cp16(s_ + 16384 + (t + i_ * 256) * 16, gb_ + i_ * 256);     \
        CP_COMMIT();                                                    \
    } while (0)

    float acc[4][4][4];
#pragma unroll
    for (int i = 0; i < 4; i++)
#pragma unroll
        for (int j = 0; j < 4; j++)
#pragma unroll
            for (int r = 0; r < 4; r++) acc[i][j][r] = 0.f;

    LOADS(0, 0);
    LOADS(1, 1);

    uint32_t ah[2][4][4], bh[2][4][2];

    for (int c = 0; c < 8; c++) {
        if (c < 6) CP_WAIT(1);
        else       CP_WAIT(0);
        __syncthreads();

        if (c + 2 < 8) LOADS(c + 2, (c + 2) % 3);

        const uint32_t sa = sb + (c % 3) * 32768;
        const uint32_t sbm = sa + 16384;

#define AADDR(kb, i) (sa + (uint32_t)(((kb) >> 1) * 8192 + \
                       (((wm * 4 + (i)) * 2 + ((kb) & 1)) * 512 + lane * 16)))
#define BADDR(kb, j) (sbm + (uint32_t)(((kb) >> 1) * 8192 + \
                       (((wn * 4 + (j)) * 2 + ((kb) & 1)) * 256 + lane * 8)))

#pragma unroll
        for (int i = 0; i < 4; i++) lds128(ah[0][i], AADDR(0, i));
#pragma unroll
        for (int j = 0; j < 4; j++) lds64(bh[0][j], BADDR(0, j));

#pragma unroll
        for (int kb = 0; kb < 4; kb++) {
            const int cur = kb & 1, nxt = cur ^ 1;
            if (kb < 3) {
#pragma unroll
                for (int i = 0; i < 4; i++) lds128(ah[nxt][i], AADDR(kb + 1, i));
#pragma unroll
                for (int j = 0; j < 4; j++) lds64(bh[nxt][j], BADDR(kb + 1, j));
            }
#pragma unroll
            for (int i = 0; i < 4; i++)
#pragma unroll
                for (int j = 0; j < 4; j++)
                    mma_fp16(acc[i][j], ah[cur][i], bh[cur][j]);
        }
#undef AADDR
#undef BADDR
    }

    // epilogue: fp16 output (bias added in fp32, rounded once)
    const int row0 = blockIdx.x * 128 + wm * 64 + (lane >> 2);
    const int colb = blockIdx.y * 128 + wn * 32 + (lane & 3) * 2;
#pragma unroll
    for (int i = 0; i < 4; i++)
#pragma unroll
        for (int j = 0; j < 4; j++) {
            const int r = row0 + i * 16;
            const int c = colb + j * 8;
            const float b0 = __ldg(g_bias + c), b1 = __ldg(g_bias + c + 1);
            __half2 h0 = __floats2half2_rn(acc[i][j][0] + b0, acc[i][j][1] + b1);
            __half2 h1 = __floats2half2_rn(acc[i][j][2] + b0, acc[i][j][3] + b1);
            *(__half2*)(g_qkv + (size_t)r * 1536 + c) = h0;
            *(__half2*)(g_qkv + (size_t)(r + 8) * 1536 + c) = h1;
        }
#undef LOADS
}

// --------------------- GEMM out-proj: 64x128 tiles (R9) --------------------
#define GOSMEM (3 * 24576)

__global__ __launch_bounds__(256, 2)
void gemm_o(const float* __restrict__ bias, float* __restrict__ C)
{
    extern __shared__ __align__(16) char smem[];
    const uint32_t sb = s2u32(smem);
    const int t = threadIdx.x;
    const int wid = t >> 5, lane = t & 31;
    const int wm = wid & 1, wn = wid >> 1;

    const int mtile = blockIdx.x >> 1, mh = blockIdx.x & 1;
    const uint4* Ag = (const uint4*)g_aatt + (size_t)mtile * 8192;
    const uint4* Bg = (const uint4*)g_bw2 + (size_t)blockIdx.y * 8192;

#define LOADO(c, stage) do {                                            \
        uint32_t s_ = sb + (stage) * 24576;                             \
        const uint4* ga0_ = Ag + (c) * 1024 + mh * 256 + t;             \
        const uint4* ga1_ = Ag + (c) * 1024 + 512 + mh * 256 + t;       \
        cp16(s_ + t * 16, ga0_);                                        \
        cp16(s_ + 4096 + t * 16, ga1_);                                 \
        const uint4* gb_ = Bg + (c) * 1024 + t;                         \
        _Pragma("unroll")                                               \
        for (int i_ = 0; i_ < 4; i_++)                                  \
            cp16(s_ + 8192 + (t + i_ * 256) * 16, gb_ + i_ * 256);      \
        CP_COMMIT();                                                    \
    } while (0)

    float acc[2][4][4];
#pragma unroll
    for (int i = 0; i < 2; i++)
#pragma unroll
        for (int j = 0; j < 4; j++)
#pragma unroll
            for (int r = 0; r < 4; r++) acc[i][j][r] = 0.f;

    LOADO(0, 0);
    LOADO(1, 1);

    uint32_t ah[2][2][4], bh[2][4][2];

    for (int c = 0; c < 8; c++) {
        if (c < 6) CP_WAIT(1);
        else       CP_WAIT(0);
        __syncthreads();

        if (c + 2 < 8) LOADO(c + 2, (c + 2) % 3);

        const uint32_t sa = sb + (c % 3) * 24576;
        const uint32_t sbm = sa + 8192;

#define AADDR(kb, i) (sa + (uint32_t)(((kb) >> 1) * 4096 + \
                       (((wm * 2 + (i)) * 2 + ((kb) & 1)) * 512 + lane * 16)))
#define BADDR(kb, j) (sbm + (uint32_t)(((kb) >> 1) * 8192 + \
                       (((wn * 4 + (j)) * 2 + ((kb) & 1)) * 256 + lane * 8)))

#pragma unroll
        for (int i = 0; i < 2; i++) lds128(ah[0][i], AADDR(0, i));
#pragma unroll
        for (int j = 0; j < 4; j++) lds64(bh[0][j], BADDR(0, j));

#pragma unroll
        for (int kb = 0; kb < 4; kb++) {
            const int cur = kb & 1, nxt = cur ^ 1;
            if (kb < 3) {
#pragma unroll
                for (int i = 0; i < 2; i++) lds128(ah[nxt][i], AADDR(kb + 1, i));
#pragma unroll
                for (int j = 0; j < 4; j++) lds64(bh[nxt][j], BADDR(kb + 1, j));
            }
#pragma unroll
            for (int i = 0; i < 2; i++)
#pragma unroll
                for (int j = 0; j < 4; j++)
                    mma_fp16(acc[i][j], ah[cur][i], bh[cur][j]);
        }
#undef AADDR
#undef BADDR
    }

    const int row0 = blockIdx.x * 64 + wm * 32 + (lane >> 2);
    const int colb = blockIdx.y * 128 + wn * 32 + (lane & 3) * 2;
#pragma unroll
    for (int i = 0; i < 2; i++)
#pragma unroll
        for (int j = 0; j < 4; j++) {
            const int r = row0 + i * 16;
            const int c = colb + j * 8;
            const float b0 = __ldg(bias + c), b1 = __ldg(bias + c + 1);
            *(float2*)(C + (size_t)r * 512 + c) =
                make_float2(acc[i][j][0] + b0, acc[i][j][1] + b1);
            *(float2*)(C + (size_t)(r + 8) * 512 + c) =
                make_float2(acc[i][j][2] + b0, acc[i][j][3] + b1);
        }
#undef LOADO
}

// ----------------------------- attention -----------------------------------
// block=(bm, head).
//  P1: stage sp + Q/K/V rows via coalesced uint4 loads.
//  P2: build Q/K mma fragments from smem; Gram S = Q@K^T via 18 mmas.
//  P3: warp-per-query softmax over 17 S entries + scalar V loop +
//      shfl-free fp16 fragment pack (lane owns column pair).
__global__ __launch_bounds__(256)
void attn_kernel(const int* __restrict__ pair_idxs)
{
    __shared__ __align__(16) int      sp[45 * 17];
    __shared__ __align__(16) __half   qsh[45 * 64];
    __shared__ __align__(16) __half   ksh[45 * 64];
    __shared__ __align__(16) __half2  vs2[45 * 32];
    __shared__ __align__(16) uint32_t qf[1536];   // Q A-frags: [mb(3)][kb(4)][128]
    __shared__ __align__(16) uint32_t kf[1536];   // K B-frags: [nb(6)][kb(4)][64]
    __shared__ __align__(16) float    S[48 * 52];

    const int bm = blockIdx.x;   // 0..255
    const int n = blockIdx.y;    // 0..7
    const int base = bm * 45;
    const int tid = threadIdx.x;

    for (int i = tid; i < 45 * 17; i += 256) sp[i] = pair_idxs[i];
    // coalesced stage of q/k/v head slices (45 rows x 8 uint4 each)
    for (int i = tid; i < 45 * 8; i += 256) {
        const int r = i >> 3, seg = i & 7;
        const __half* src = g_qkv + (size_t)(base + r) * 1536 + n * 64;
        ((uint4*)qsh)[r * 8 + seg] = ((const uint4*)src)[seg];
        ((uint4*)ksh)[r * 8 + seg] = ((const uint4*)(src + 512))[seg];
        ((uint4*)vs2)[r * 8 + seg] = ((const uint4*)(src + 1024))[seg];
    }
    __syncthreads();

    // build Q fragments from smem
    for (int p = tid; p < 1536; p += 256) {
        const int mbkb = p >> 7, q = p & 127;
        const int mb = mbkb >> 2, kb = mbkb & 3;
        const int lane = q >> 2, reg = q & 3;
        const int row = mb * 16 + (lane >> 2) + 8 * (reg & 1);
        const int col = kb * 16 + (lane & 3) * 2 + 8 * (reg >> 1);
        qf[p] = (row < 45) ? *(const uint32_t*)&qsh[row * 64 + col] : 0u;
    }
    // build K fragments from smem
    for (int p = tid; p < 1536; p += 256) {
        const int nbkb = p >> 6, q = p & 63;
        const int nb = nbkb >> 2, kb = nbkb & 3;
        const int lane = q >> 1, reg = q & 1;
        const int nr = nb * 8 + (lane >> 2);
        const int col = kb * 16 + (lane & 3) * 2 + 8 * reg;
        kf[p] = (nr < 45) ? *(const uint32_t*)&ksh[nr * 64 + col] : 0u;
    }
    __syncthreads();

    const int warp = tid >> 5, lane = tid & 31;
    const uint32_t qfb = s2u32(qf), kfb = s2u32(kf);

    // Gram: 18 tiles of 16x8, 4 k-steps each
    for (int t = warp; t < 18; t += 8) {
        const int mb = t / 6, nb = t % 6;
        float c[4] = {0.f, 0.f, 0.f, 0.f};
#pragma unroll
        for (int kb = 0; kb < 4; kb++) {
            uint32_t a[4], b[2];
            lds128(a, qfb + (uint32_t)(((mb * 4 + kb) * 128 + lane * 4) * 4));
            lds64(b, kfb + (uint32_t)(((nb * 4 + kb) * 64 + lane * 2) * 4));
            mma_fp16(c, a, b);
        }
        const int r0 = mb * 16 + (lane >> 2);
        const int c0 = nb * 8 + (lane & 3) * 2;
        *(float2*)&S[r0 * 52 + c0] = make_float2(c[0], c[1]);
        *(float2*)&S[(r0 + 8) * 52 + c0] = make_float2(c[2], c[3]);
    }
    __syncthreads();

    // softmax + V + fragment pack (lane owns column pair 2*lane, 2*lane+1)
    for (int tt = warp; tt < 45; tt += 8) {
        float sc[17];
        int tj[17];
#pragma unroll
        for (int j = 0; j < 17; j++) {
            tj[j] = sp[tt * 17 + j];
            sc[j] = S[tt * 52 + tj[j]] * 0.125f;   // broadcast LDS
        }
        float mx = sc[0];
#pragma unroll
        for (int j = 1; j < 17; j++) mx = fmaxf(mx, sc[j]);
        float ssum = 0.f;
#pragma unroll
        for (int j = 0; j < 17; j++) { sc[j] = __expf(sc[j] - mx); ssum += sc[j]; }
        const float inv = 1.f / ssum;

        float ox = 0.f, oy = 0.f;
#pragma unroll
        for (int j = 0; j < 17; j++) {
            const float2 fv = __half22float2(vs2[tj[j] * 32 + lane]);
            const float w = sc[j] * inv;
            ox += w * fv.x;
            oy += w * fv.y;
        }

        const int grow = base + tt;
        const int mtile = grow >> 7;
        const int rr = grow & 127;
        const int rbit = (rr >> 3) & 1;
        const int mb = rr >> 4;
        const int jp = lane;                     // pair index 0..31
        const int kc = n * 2 + (jp >> 4);
        const int jpl = jp & 15;
        const int lane_t = (rr & 7) * 4 + (jpl & 3);
        const int reg = rbit + 2 * ((jpl >> 2) & 1);
        const int kb = jpl >> 3;
        const int idx = (mb * 2 + kb) * 128 + lane_t * 4 + reg;

        __half2 h = __floats2half2_rn(ox, oy);
        g_aatt[((size_t)mtile * 16 + kc) * 2048 + idx] = *(uint32_t*)&h;
    }
}

// ------------------------------- launch ------------------------------------
extern "C" void kernel_launch(void* const* d_in, const int* in_sizes, int n_in,
                              void* d_out, int out_size)
{
    const float* x  = (const float*)d_in[0];
    const float* Wq = (const float*)d_in[1];
    const float* bq = (const float*)d_in[2];
    const float* Wk = (const float*)d_in[3];
    const float* bk = (const float*)d_in[4];
    const float* Wv = (const float*)d_in[5];
    const float* bv = (const float*)d_in[6];
    const float* Wp = (const float*)d_in[7];
    const float* bp = (const float*)d_in[8];
    const int* pair = (const int*)d_in[9];
    float* out = (float*)d_out;
    (void)in_sizes; (void)n_in; (void)out_size;

    cudaFuncSetAttribute(gemm_qkv, cudaFuncAttributeMaxDynamicSharedMemorySize, GSMEM);
    cudaFuncSetAttribute(gemm_o, cudaFuncAttributeMaxDynamicSharedMemorySize, GOSMEM);

    pack_all<<<1696, 256>>>(x, Wq, Wk, Wv, Wp, bq, bk, bv);
    gemm_qkv<<<dim3(90, 12), 256, GSMEM>>>();
    attn_kernel<<<dim3(256, 8), 256>>>(pair);
    gemm_o<<<dim3(180, 4), 256, GOSMEM>>>(bp, out);
}